// round 15
// baseline (speedup 1.0000x reference)
#include <cuda_runtime.h>
#include <cuda_fp16.h>
#include <cstdint>

// Problem constants
#define NN 50000
#define EE 800000
#define BB 4
#define CC 64
#define NROWS (BB*NN)
#define SBS 256
#define SNB ((NN + SBS - 1) / SBS)

// ---------------- scratch (device globals) ----------------
__device__ int    g_deg[NN];          // zero at load; re-zeroed by k_fill3 each run
__device__ float  g_norm[NN];
__device__ int    g_rowptr[NN + 1];
__device__ int    g_rank[EE];         // edge rank within its dst bucket
__device__ int    g_esrc[EE];         // CSR edge src
__device__ __half g_xh[(size_t)NROWS * CC];    // x (fp16, GEMM operand)
__device__ __half g_xt[(size_t)NROWS * CC];    // x~ = norm[s]*x (gather operand)
__device__ __half g_y1h[(size_t)NROWS * CC];   // y1 (GEMM operand)
__device__ __half g_y1t[(size_t)NROWS * CC];   // norm*y1 (gather operand)
__device__ __half g_zh[(size_t)NROWS * CC];    // z = A y1 (GEMM operand)

// ---------------- fp16 mma helper ----------------
__device__ __forceinline__ unsigned pkh2(float a, float b) {
    __half2 h = __floats2half2_rn(a, b);
    return *(unsigned*)&h;
}
__device__ __forceinline__ void mma16(float* c,
                                      unsigned a0, unsigned a1, unsigned a2, unsigned a3,
                                      unsigned b0, unsigned b1) {
    asm volatile("mma.sync.aligned.m16n8k16.row.col.f32.f16.f16.f32 "
                 "{%0,%1,%2,%3}, {%4,%5,%6,%7}, {%8,%9}, {%0,%1,%2,%3};"
                 : "+f"(c[0]), "+f"(c[1]), "+f"(c[2]), "+f"(c[3])
                 : "r"(a0), "r"(a1), "r"(a2), "r"(a3), "r"(b0), "r"(b1));
}

// ---------------- launch 1: degree + rank + x->fp16 (xh) ----------------
// 800k threads: one atomic each (latency-bound) + 16-float convert rides free.
__global__ void k_degree(const int* __restrict__ dst, const float* __restrict__ x) {
    const int tid = blockIdx.x * blockDim.x + threadIdx.x;

    const size_t i16 = (size_t)tid * 16;
    if (i16 < (size_t)NROWS * CC) {
#pragma unroll
        for (int h = 0; h < 2; h++) {
            const size_t i8 = i16 + h * 8;
            float4 a = *(const float4*)(x + i8);
            float4 b = *(const float4*)(x + i8 + 4);
            __half2 hv[4];
            hv[0] = __floats2half2_rn(a.x, a.y);
            hv[1] = __floats2half2_rn(a.z, a.w);
            hv[2] = __floats2half2_rn(b.x, b.y);
            hv[3] = __floats2half2_rn(b.z, b.w);
            *(uint4*)(g_xh + i8) = *(uint4*)hv;
        }
    }

    if (tid < EE) g_rank[tid] = atomicAdd(&g_deg[dst[tid]], 1);
}

// ---------------- launch 2: scan + emit ----------------
__global__ void k_emit2() {
    __shared__ int sh[SBS];
    const int t = threadIdx.x;
    const int i = blockIdx.x * SBS + t;

    const int lim = blockIdx.x * SBS;      // multiple of 256 -> int4-aligned
    int s = 0;
    for (int j = t * 4; j < lim; j += SBS * 4) {
        int4 v = *(const int4*)(g_deg + j);
        s += v.x + v.y + v.z + v.w;
    }
    sh[t] = s;
    __syncthreads();
    for (int off = SBS / 2; off > 0; off >>= 1) {
        if (t < off) sh[t] += sh[t + off];
        __syncthreads();
    }
    const int boff = sh[0];
    __syncthreads();

    const int d = (i < NN) ? g_deg[i] : 0;
    sh[t] = d;
    __syncthreads();
    for (int off = 1; off < SBS; off <<= 1) {
        int u = (t >= off) ? sh[t - off] : 0;
        __syncthreads();
        sh[t] += u;
        __syncthreads();
    }
    if (i < NN) {
        g_rowptr[i] = boff + sh[t] - d;    // exclusive prefix
        g_norm[i]   = rsqrtf((float)(d < 1 ? 1 : d));
    }
    if (i == 0) g_rowptr[NN] = EE;
}

// ---------------- launch 3: edge fill (atomic-free) + xt from xh -------------
__global__ void k_fill3(const int* __restrict__ src, const int* __restrict__ dst) {
    const int tid = blockIdx.x * blockDim.x + threadIdx.x;

    // xt = fp16(norm[node] * xh)   (8 halves/thread, reads fp16 not fp32)
    const size_t i8 = (size_t)tid * 8;
    if (i8 < (size_t)NROWS * CC) {
        const int row  = (int)(i8 >> 6);           // /CC
        const int node = row % NN;
        const float nm = g_norm[node];
        uint4 hv = *(const uint4*)(g_xh + i8);
        const __half2* hp = (const __half2*)&hv;
        __half2 ht[4];
#pragma unroll
        for (int j = 0; j < 4; j++) {
            float2 f = __half22float2(hp[j]);
            ht[j] = __floats2half2_rn(nm * f.x, nm * f.y);
        }
        *(uint4*)(g_xt + i8) = *(uint4*)ht;
    }

    if (tid < EE) {
        const int d = dst[tid];
        g_esrc[g_rowptr[d] + g_rank[tid]] = src[tid];
    }

    // re-zero g_deg for the next replay (nothing reads g_deg after k_emit2)
    if (tid < NN / 4) ((int4*)g_deg)[tid] = make_int4(0, 0, 0, 0);
}

// ---------------- launches 4,5: SPMM (weight-hoisted, fp16 HADD2 acc) --------
// AT THE LTS THROUGHPUT CAP (410MB L2 reads / ~32us) — known-good, frozen.
__global__ void k_spmm_h(const __half* __restrict__ in_t,
                         __half* __restrict__ out_h,
                         __half* __restrict__ out_t,
                         float alpha) {
    const int warp = (blockIdx.x * blockDim.x + threadIdx.x) >> 5;
    if (warp >= NN) return;
    const int node = warp;
    const int lane = threadIdx.x & 31;
    const int b  = lane >> 3;
    const int c8 = (lane & 7) * 8;

    const __half* base = in_t + (size_t)b * NN * CC + c8;

    __half2 z2 = __float2half2_rn(0.f);
    __half2 acc0[4] = {z2, z2, z2, z2};
    __half2 acc1[4] = {z2, z2, z2, z2};

    const int s0 = g_rowptr[node];
    const int s1 = g_rowptr[node + 1];

    int e = s0;
    for (; e + 4 <= s1; e += 4) {
        const int sA = g_esrc[e];
        const int sB = g_esrc[e + 1];
        const int sC = g_esrc[e + 2];
        const int sD = g_esrc[e + 3];
        uint4 vA = *(const uint4*)(base + (size_t)sA * CC);
        uint4 vB = *(const uint4*)(base + (size_t)sB * CC);
        uint4 vC = *(const uint4*)(base + (size_t)sC * CC);
        uint4 vD = *(const uint4*)(base + (size_t)sD * CC);
        const __half2* hA = (const __half2*)&vA;
        const __half2* hB = (const __half2*)&vB;
        const __half2* hC = (const __half2*)&vC;
        const __half2* hD = (const __half2*)&vD;
#pragma unroll
        for (int j = 0; j < 4; j++) {
            acc0[j] = __hadd2(acc0[j], hA[j]);
            acc1[j] = __hadd2(acc1[j], hB[j]);
            acc0[j] = __hadd2(acc0[j], hC[j]);
            acc1[j] = __hadd2(acc1[j], hD[j]);
        }
    }
    if (e + 2 <= s1) {
        const int sA = g_esrc[e];
        const int sB = g_esrc[e + 1];
        uint4 vA = *(const uint4*)(base + (size_t)sA * CC);
        uint4 vB = *(const uint4*)(base + (size_t)sB * CC);
        const __half2* hA = (const __half2*)&vA;
        const __half2* hB = (const __half2*)&vB;
#pragma unroll
        for (int j = 0; j < 4; j++) {
            acc0[j] = __hadd2(acc0[j], hA[j]);
            acc1[j] = __hadd2(acc1[j], hB[j]);
        }
        e += 2;
    }
    if (e < s1) {
        uint4 v = *(const uint4*)(base + (size_t)g_esrc[e] * CC);
        const __half2* hp = (const __half2*)&v;
#pragma unroll
        for (int j = 0; j < 4; j++) acc0[j] = __hadd2(acc0[j], hp[j]);
    }

    const float nrm = g_norm[node];
    const float sc  = alpha * nrm;

    float r[8];
#pragma unroll
    for (int j = 0; j < 4; j++) {
        float2 f0 = __half22float2(acc0[j]);
        float2 f1 = __half22float2(acc1[j]);
        r[2 * j]     = sc * (f0.x + f1.x);
        r[2 * j + 1] = sc * (f0.y + f1.y);
    }

    const size_t o = ((size_t)b * NN + node) * CC + c8;
    __half2 h[4];
    h[0] = __floats2half2_rn(r[0], r[1]);
    h[1] = __floats2half2_rn(r[2], r[3]);
    h[2] = __floats2half2_rn(r[4], r[5]);
    h[3] = __floats2half2_rn(r[6], r[7]);
    *(uint4*)(out_h + o) = *(uint4*)h;

    if (out_t != nullptr) {
        __half2 ht[4];
        ht[0] = __floats2half2_rn(nrm * r[0], nrm * r[1]);
        ht[1] = __floats2half2_rn(nrm * r[2], nrm * r[3]);
        ht[2] = __floats2half2_rn(nrm * r[4], nrm * r[5]);
        ht[3] = __floats2half2_rn(nrm * r[6], nrm * r[7]);
        *(uint4*)(out_t + o) = *(uint4*)ht;
    }
}

// ---------------- launch 6: fused dense via fp16 mma m16n8k16 ----------------
// Folded form:  h = relu( x*(W0-W2) + y1*W1 + z*(-2*W2) + bc ),  out = h*Wl + bl
// CTA: 128 rows x 64 cols, 512 threads (16 warps), warp tile 16x32.
// A-fragment smem layout uses lane permutation lperm = (lane&3)*8 + (lane>>2)
// so staging runs as 4x LDG.128 + 4x STS.128 per (kt,rt,gg) group.
#define TR 128
#define NKT1 12          // phase-1 k16-steps (K=192)
#define NKT2 4           // phase-2 k16-steps (K=64)
#define BSTRIDE 20       // Bf slot stride in floats (16 data + 4 pad, conflict-free)

__global__ void __launch_bounds__(512, 2)
k_fused(const float* __restrict__ Wc, const float* __restrict__ bc,
        const float* __restrict__ Wl, const float* __restrict__ bl,
        float* __restrict__ out) {
    extern __shared__ float sm[];
    float* Af  = sm;                         // 12*8*32*4 = 12288 f (A frags, f16x2)
    float* Bf  = sm + NKT1 * 8 * 32 * 4;     // 12*32*20  =  7680 f (Wc frags, folded)
    float* Bl2 = Bf + NKT1 * 32 * BSTRIDE;   //  4*32*20  =  2560 f (Wl frags)
    float* bcs = Bl2 + NKT2 * 32 * BSTRIDE;  // 64
    float* bls = bcs + 64;                   // 64
    float* Hs  = Af;                         // overlay: 4*8*32*4 f (phase2 A)

    const int t    = threadIdx.x;
    const int lane = t & 31;
    const int w    = t >> 5;
    const int rowbase = blockIdx.x * TR;
    const int nrows = min(TR, NROWS - rowbase);

    // ---- stage Bf: folded Wc -> fp16 B fragments ----
    // seg0 (k<64): W0 - W2 ;  seg1: W1 ;  seg2 (k>=128): -2*W2
    for (int s = t; s < NKT1 * 32; s += 512) {
        const int kt = s >> 5, ln = s & 31;
        const int gg = ln >> 2, tt = ln & 3;
        const int k0 = kt * 16 + 2 * tt;
        unsigned v[16];
#pragma unroll
        for (int nt = 0; nt < 8; nt++) {
            const int n = nt * 8 + gg;
            float f[4];
#pragma unroll
            for (int q = 0; q < 4; q++) {
                const int k = k0 + (q & 1) + (q >> 1) * 8;   // k0, k0+1, k0+8, k0+9
                float val = Wc[k * 64 + n];
                if (kt < 4)       val -= Wc[(k + 128) * 64 + n];   // W0 - W2
                else if (kt >= 8) val = -2.f * val;                // -2*W2
                f[q] = val;
            }
            v[nt * 2]     = pkh2(f[0], f[1]);
            v[nt * 2 + 1] = pkh2(f[2], f[3]);
        }
        uint4* dp = (uint4*)(Bf + s * BSTRIDE);
        dp[0] = make_uint4(v[0],  v[1],  v[2],  v[3]);
        dp[1] = make_uint4(v[4],  v[5],  v[6],  v[7]);
        dp[2] = make_uint4(v[8],  v[9],  v[10], v[11]);
        dp[3] = make_uint4(v[12], v[13], v[14], v[15]);
    }
    // ---- stage Bl2: Wl[64][64] ----
    for (int s = t; s < NKT2 * 32; s += 512) {
        const int kt = s >> 5, ln = s & 31;
        const int gg = ln >> 2, tt = ln & 3;
        const int k0 = kt * 16 + 2 * tt;
        unsigned v[16];
#pragma unroll
        for (int nt = 0; nt < 8; nt++) {
            const int n = nt * 8 + gg;
            v[nt * 2]     = pkh2(Wl[(k0)     * 64 + n], Wl[(k0 + 1) * 64 + n]);
            v[nt * 2 + 1] = pkh2(Wl[(k0 + 8) * 64 + n], Wl[(k0 + 9) * 64 + n]);
        }
        uint4* dp = (uint4*)(Bl2 + s * BSTRIDE);
        dp[0] = make_uint4(v[0],  v[1],  v[2],  v[3]);
        dp[1] = make_uint4(v[4],  v[5],  v[6],  v[7]);
        dp[2] = make_uint4(v[8],  v[9],  v[10], v[11]);
        dp[3] = make_uint4(v[12], v[13], v[14], v[15]);
    }
    if (t < 64) { bcs[t] = bc[t]; bls[t] = bl[t]; }

    // ---- stage Af: U = [xh | y1h | zh], wide loads, lperm slot layout ----
    // group idx = (kt, rt, gg): loads rows 16rt+gg and +8, halves [16kt, 16kt+16)
    // slot (tt*8+gg) gets {a0,a1,a2,a3} for frag-thread (g=gg, tid=tt).
    for (int idx = t; idx < NKT1 * 64; idx += 512) {
        const int kt  = idx >> 6;
        const int rem = idx & 63;
        const int rt  = rem >> 3;
        const int gg  = rem & 7;
        const __half* p = (kt < 4) ? g_xh : (kt < 8) ? g_y1h : g_zh;
        const int c0 = (kt & 3) * 16;
        const int r0 = rt * 16 + gg;
        const __half* pr = p + (size_t)rowbase * CC;
        uint4 lo0 = make_uint4(0, 0, 0, 0), hi0 = make_uint4(0, 0, 0, 0);
        uint4 lo1 = make_uint4(0, 0, 0, 0), hi1 = make_uint4(0, 0, 0, 0);
        if (r0 < nrows) {
            lo0 = *(const uint4*)(pr + (size_t)r0 * CC + c0);
            hi0 = *(const uint4*)(pr + (size_t)r0 * CC + c0 + 8);
        }
        if (r0 + 8 < nrows) {
            lo1 = *(const uint4*)(pr + (size_t)(r0 + 8) * CC + c0);
            hi1 = *(const uint4*)(pr + (size_t)(r0 + 8) * CC + c0 + 8);
        }
        const unsigned* l0 = (const unsigned*)&lo0;
        const unsigned* l1 = (const unsigned*)&lo1;
        const unsigned* h0 = (const unsigned*)&hi0;
        const unsigned* h1 = (const unsigned*)&hi1;
        float* bs = Af + ((kt * 8 + rt) * 32) * 4;
#pragma unroll
        for (int tt = 0; tt < 4; tt++) {
            *(uint4*)(bs + (tt * 8 + gg) * 4) =
                make_uint4(l0[tt], l1[tt], h0[tt], h1[tt]);
        }
    }
    __syncthreads();

    const int mtile = w >> 1;     // 0..7 -> rows 16*mtile
    const int nt2   = w & 1;      // 0..1 -> cols 32*nt2
    const int g = lane >> 2, tid = lane & 3;
    const int lperm = tid * 8 + g;          // permuted slot index for this lane

    // ---- phase 1: h = U @ Wc_folded ----
    float c1[4][4];
#pragma unroll
    for (int n = 0; n < 4; n++)
#pragma unroll
        for (int q = 0; q < 4; q++) c1[n][q] = 0.f;

#pragma unroll
    for (int kt = 0; kt < NKT1; kt++) {
        const uint4 A = *(const uint4*)(Af + ((kt * 8 + mtile) * 32 + lperm) * 4);
        const float* bp = Bf + (kt * 32 + lane) * BSTRIDE + nt2 * 8;
        const uint4 B0 = *(const uint4*)(bp);
        const uint4 B1 = *(const uint4*)(bp + 4);
        mma16(c1[0], A.x, A.y, A.z, A.w, B0.x, B0.y);
        mma16(c1[1], A.x, A.y, A.z, A.w, B0.z, B0.w);
        mma16(c1[2], A.x, A.y, A.z, A.w, B1.x, B1.y);
        mma16(c1[3], A.x, A.y, A.z, A.w, B1.z, B1.w);
    }
    __syncthreads();   // all Af reads complete before Hs overlay

    // ---- epilogue 1: bias + relu -> fp16 A-fragments into Hs (lperm layout) --
#pragma unroll
    for (int j = 0; j < 2; j++) {
        const int kt2 = 2 * nt2 + j;
        float v[4][2];
#pragma unroll
        for (int h = 0; h < 2; h++) {
            const int n = 2 * j + h;
            const int Cl = nt2 * 32 + n * 8 + 2 * tid;
            const float b0 = bcs[Cl], b1 = bcs[Cl + 1];
            v[2 * h][0]     = fmaxf(c1[n][0] + b0, 0.f);
            v[2 * h][1]     = fmaxf(c1[n][1] + b1, 0.f);
            v[2 * h + 1][0] = fmaxf(c1[n][2] + b0, 0.f);
            v[2 * h + 1][1] = fmaxf(c1[n][3] + b1, 0.f);
        }
        *(uint4*)(Hs + ((kt2 * 8 + mtile) * 32 + lperm) * 4) =
            make_uint4(pkh2(v[0][0], v[0][1]), pkh2(v[1][0], v[1][1]),
                       pkh2(v[2][0], v[2][1]), pkh2(v[3][0], v[3][1]));
    }
    __syncthreads();

    // ---- phase 2: out = h @ Wl ----
    float c2[4][4];
#pragma unroll
    for (int n = 0; n < 4; n++)
#pragma unroll
        for (int q = 0; q < 4; q++) c2[n][q] = 0.f;

#pragma unroll
    for (int kt = 0; kt < NKT2; kt++) {
        const uint4 A = *(const uint4*)(Hs + ((kt * 8 + mtile) * 32 + lperm) * 4);
        const float* bp = Bl2 + (kt * 32 + lane) * BSTRIDE + nt2 * 8;
        const uint4 B0 = *(const uint4*)(bp);
        const uint4 B1 = *(const uint4*)(bp + 4);
        mma16(c2[0], A.x, A.y, A.z, A.w, B0.x, B0.y);
        mma16(c2[1], A.x, A.y, A.z, A.w, B0.z, B0.w);
        mma16(c2[2], A.x, A.y, A.z, A.w, B1.x, B1.y);
        mma16(c2[3], A.x, A.y, A.z, A.w, B1.z, B1.w);
    }

    // ---- epilogue 2: bias + store ----
#pragma unroll
    for (int n = 0; n < 4; n++) {
        const int Cl = nt2 * 32 + n * 8 + 2 * tid;
        const float b0 = bls[Cl], b1 = bls[Cl + 1];
        const int Rl = mtile * 16 + g;
        if (Rl < nrows)
            *(float2*)(out + (size_t)(rowbase + Rl) * CC + Cl) =
                make_float2(c2[n][0] + b0, c2[n][1] + b1);
        if (Rl + 8 < nrows)
            *(float2*)(out + (size_t)(rowbase + Rl + 8) * CC + Cl) =
                make_float2(c2[n][2] + b0, c2[n][3] + b1);
    }
}

// ---------------- launch ----------------
extern "C" void kernel_launch(void* const* d_in, const int* in_sizes, int n_in,
                              void* d_out, int out_size) {
    const float* x   = (const float*)d_in[0];
    const int*   src = (const int*)d_in[1];
    const int*   dst = (const int*)d_in[2];
    const float* Wc  = (const float*)d_in[3];
    const float* bc  = (const float*)d_in[4];
    const float* Wl  = (const float*)d_in[5];
    const float* bl  = (const float*)d_in[6];
    float* out = (float*)d_out;

    const int fused_smem = (NKT1 * 8 * 32 * 4 + NKT1 * 32 * BSTRIDE +
                            NKT2 * 32 * BSTRIDE + 128) * 4;   // 90624 B
    static bool attr_set = false;
    if (!attr_set) {
        cudaFuncSetAttribute(k_fused, cudaFuncAttributeMaxDynamicSharedMemorySize,
                             fused_smem);
        attr_set = true;
    }

    __half *xt, *y1h, *y1t, *zh;
    cudaGetSymbolAddress((void**)&xt,  g_xt);
    cudaGetSymbolAddress((void**)&y1h, g_y1h);
    cudaGetSymbolAddress((void**)&y1t, g_y1t);
    cudaGetSymbolAddress((void**)&zh,  g_zh);

    // 1: degrees + edge ranks + xh convert (atomic latency hides the convert)
    k_degree<<<(EE + 255) / 256, 256>>>(dst, x);
    // 2: rowptr + norm
    k_emit2<<<SNB, SBS>>>();
    // 3: atomic-free edge fill + xt = norm*xh + re-zero deg
    k_fill3<<<(NROWS * CC / 8 + 255) / 256, 256>>>(src, dst);
    // 4: y1 = -norm[d] * sum(x~[src]) ; also y1t = norm*y1 for the next gather
    k_spmm_h<<<(NN + 7) / 8, 256>>>(xt, y1h, y1t, -1.f);
    // 5: z = norm[d] * sum(y1t[src]) = A y1   (y2 folded into GEMM weights)
    k_spmm_h<<<(NN + 7) / 8, 256>>>(y1t, zh, nullptr, 1.f);
    // 6: fused dense (fp16 tensor cores, folded weights, wide-load staging)
    const int nblk = (NROWS + TR - 1) / TR;
    k_fused<<<nblk, 512, fused_smem>>>(Wc, bc, Wl, bl, out);
}

// round 16
// speedup vs baseline: 1.1780x; 1.1780x over previous
#include <cuda_runtime.h>
#include <cuda_fp16.h>
#include <cstdint>

// Problem constants
#define NN 50000
#define EE 800000
#define BB 4
#define CC 64
#define NROWS (BB*NN)
#define SBS 256
#define SNB ((NN + SBS - 1) / SBS)

// fused-kernel geometry (needed for weight-fragment globals)
#define TR 128
#define NKT1 12          // phase-1 k16-steps (K=192)
#define NKT2 4           // phase-2 k16-steps (K=64)
#define BSTRIDE 20       // Bf slot stride in floats (16 data + 4 pad, conflict-free)

// ---------------- scratch (device globals) ----------------
__device__ int    g_deg[NN];          // zero at load; re-zeroed by k_fill3 each run
__device__ float  g_norm[NN];
__device__ int    g_rowptr[NN + 1];
__device__ int    g_rank[EE];         // edge rank within its dst bucket
__device__ int    g_esrc[EE];         // CSR edge src
__device__ __half g_xh[(size_t)NROWS * CC];    // x (fp16, GEMM operand)
__device__ __half g_xt[(size_t)NROWS * CC];    // x~ = norm[s]*x (gather operand)
__device__ __half g_y1h[(size_t)NROWS * CC];   // y1 (GEMM operand)
__device__ __half g_y1t[(size_t)NROWS * CC];   // norm*y1 (gather operand)
__device__ __half g_zh[(size_t)NROWS * CC];    // z = A y1 (GEMM operand)
__device__ float  g_bf[NKT1 * 32 * BSTRIDE];   // prebuilt folded-Wc fragments
__device__ float  g_bl2[NKT2 * 32 * BSTRIDE];  // prebuilt Wl fragments

// ---------------- fp16 mma helper ----------------
__device__ __forceinline__ unsigned pkh2(float a, float b) {
    __half2 h = __floats2half2_rn(a, b);
    return *(unsigned*)&h;
}
__device__ __forceinline__ void mma16(float* c,
                                      unsigned a0, unsigned a1, unsigned a2, unsigned a3,
                                      unsigned b0, unsigned b1) {
    asm volatile("mma.sync.aligned.m16n8k16.row.col.f32.f16.f16.f32 "
                 "{%0,%1,%2,%3}, {%4,%5,%6,%7}, {%8,%9}, {%0,%1,%2,%3};"
                 : "+f"(c[0]), "+f"(c[1]), "+f"(c[2]), "+f"(c[3])
                 : "r"(a0), "r"(a1), "r"(a2), "r"(a3), "r"(b0), "r"(b1));
}

// ---------------- launch 0: build weight fragments ONCE ----------------
// slot s in [0, NKT1*32): folded Wc; s-NKT1*32 in [0, NKT2*32): Wl.
__global__ void k_wprep(const float* __restrict__ Wc, const float* __restrict__ Wl) {
    const int s = blockIdx.x * blockDim.x + threadIdx.x;
    if (s < NKT1 * 32) {
        const int kt = s >> 5, ln = s & 31;
        const int gg = ln >> 2, tt = ln & 3;
        const int k0 = kt * 16 + 2 * tt;
        unsigned v[16];
#pragma unroll
        for (int nt = 0; nt < 8; nt++) {
            const int n = nt * 8 + gg;
            float f[4];
#pragma unroll
            for (int q = 0; q < 4; q++) {
                const int k = k0 + (q & 1) + (q >> 1) * 8;   // k0, k0+1, k0+8, k0+9
                float val = Wc[k * 64 + n];
                if (kt < 4)       val -= Wc[(k + 128) * 64 + n];   // W0 - W2
                else if (kt >= 8) val = -2.f * val;                // -2*W2
                f[q] = val;
            }
            v[nt * 2]     = pkh2(f[0], f[1]);
            v[nt * 2 + 1] = pkh2(f[2], f[3]);
        }
        uint4* dp = (uint4*)(g_bf + s * BSTRIDE);
        dp[0] = make_uint4(v[0],  v[1],  v[2],  v[3]);
        dp[1] = make_uint4(v[4],  v[5],  v[6],  v[7]);
        dp[2] = make_uint4(v[8],  v[9],  v[10], v[11]);
        dp[3] = make_uint4(v[12], v[13], v[14], v[15]);
    } else if (s < NKT1 * 32 + NKT2 * 32) {
        const int s2 = s - NKT1 * 32;
        const int kt = s2 >> 5, ln = s2 & 31;
        const int gg = ln >> 2, tt = ln & 3;
        const int k0 = kt * 16 + 2 * tt;
        unsigned v[16];
#pragma unroll
        for (int nt = 0; nt < 8; nt++) {
            const int n = nt * 8 + gg;
            v[nt * 2]     = pkh2(Wl[(k0)     * 64 + n], Wl[(k0 + 1) * 64 + n]);
            v[nt * 2 + 1] = pkh2(Wl[(k0 + 8) * 64 + n], Wl[(k0 + 9) * 64 + n]);
        }
        uint4* dp = (uint4*)(g_bl2 + s2 * BSTRIDE);
        dp[0] = make_uint4(v[0],  v[1],  v[2],  v[3]);
        dp[1] = make_uint4(v[4],  v[5],  v[6],  v[7]);
        dp[2] = make_uint4(v[8],  v[9],  v[10], v[11]);
        dp[3] = make_uint4(v[12], v[13], v[14], v[15]);
    }
}

// ---------------- launch 1: degree + rank ----------------
__global__ void k_degree(const int* __restrict__ dst) {
    int e = blockIdx.x * blockDim.x + threadIdx.x;
    if (e < EE) g_rank[e] = atomicAdd(&g_deg[dst[e]], 1);
}

// ---------------- launch 2: scan + emit ----------------
__global__ void k_emit2() {
    __shared__ int sh[SBS];
    const int t = threadIdx.x;
    const int i = blockIdx.x * SBS + t;

    const int lim = blockIdx.x * SBS;      // multiple of 256 -> int4-aligned
    int s = 0;
    for (int j = t * 4; j < lim; j += SBS * 4) {
        int4 v = *(const int4*)(g_deg + j);
        s += v.x + v.y + v.z + v.w;
    }
    sh[t] = s;
    __syncthreads();
    for (int off = SBS / 2; off > 0; off >>= 1) {
        if (t < off) sh[t] += sh[t + off];
        __syncthreads();
    }
    const int boff = sh[0];
    __syncthreads();

    const int d = (i < NN) ? g_deg[i] : 0;
    sh[t] = d;
    __syncthreads();
    for (int off = 1; off < SBS; off <<= 1) {
        int u = (t >= off) ? sh[t - off] : 0;
        __syncthreads();
        sh[t] += u;
        __syncthreads();
    }
    if (i < NN) {
        g_rowptr[i] = boff + sh[t] - d;    // exclusive prefix
        g_norm[i]   = rsqrtf((float)(d < 1 ? 1 : d));
    }
    if (i == 0) g_rowptr[NN] = EE;
}

// ---------------- launch 3: edge fill (atomic-free) + x->fp16 (xh,xt) -------
__global__ void k_fill3(const int* __restrict__ src, const int* __restrict__ dst,
                        const float* __restrict__ x) {
    const int tid = blockIdx.x * blockDim.x + threadIdx.x;

    // xh = fp16(x), xt = fp16(norm[node]*x)   (8 elems/thread)
    const size_t i8 = (size_t)tid * 8;
    if (i8 < (size_t)NROWS * CC) {
        const int row  = (int)(i8 >> 6);           // /CC
        const int node = row % NN;
        const float nm = g_norm[node];
        float4 a = *(const float4*)(x + i8);
        float4 b = *(const float4*)(x + i8 + 4);
        __half2 h[4], ht[4];
        h[0]  = __floats2half2_rn(a.x, a.y);
        h[1]  = __floats2half2_rn(a.z, a.w);
        h[2]  = __floats2half2_rn(b.x, b.y);
        h[3]  = __floats2half2_rn(b.z, b.w);
        ht[0] = __floats2half2_rn(nm * a.x, nm * a.y);
        ht[1] = __floats2half2_rn(nm * a.z, nm * a.w);
        ht[2] = __floats2half2_rn(nm * b.x, nm * b.y);
        ht[3] = __floats2half2_rn(nm * b.z, nm * b.w);
        *(uint4*)(g_xh + i8) = *(uint4*)h;
        *(uint4*)(g_xt + i8) = *(uint4*)ht;
    }

    if (tid < EE) {
        const int d = dst[tid];
        g_esrc[g_rowptr[d] + g_rank[tid]] = src[tid];
    }

    // re-zero g_deg for the next replay (nothing reads g_deg after k_emit2)
    if (tid < NN / 4) ((int4*)g_deg)[tid] = make_int4(0, 0, 0, 0);
}

// ---------------- launches 4,5: SPMM (weight-hoisted, fp16 HADD2 acc) --------
// AT THE LTS THROUGHPUT CAP (410MB L2 reads / ~32us) — known-good, frozen.
__global__ void k_spmm_h(const __half* __restrict__ in_t,
                         __half* __restrict__ out_h,
                         __half* __restrict__ out_t,
                         float alpha) {
    const int warp = (blockIdx.x * blockDim.x + threadIdx.x) >> 5;
    if (warp >= NN) return;
    const int node = warp;
    const int lane = threadIdx.x & 31;
    const int b  = lane >> 3;
    const int c8 = (lane & 7) * 8;

    const __half* base = in_t + (size_t)b * NN * CC + c8;

    __half2 z2 = __float2half2_rn(0.f);
    __half2 acc0[4] = {z2, z2, z2, z2};
    __half2 acc1[4] = {z2, z2, z2, z2};

    const int s0 = g_rowptr[node];
    const int s1 = g_rowptr[node + 1];

    int e = s0;
    for (; e + 4 <= s1; e += 4) {
        const int sA = g_esrc[e];
        const int sB = g_esrc[e + 1];
        const int sC = g_esrc[e + 2];
        const int sD = g_esrc[e + 3];
        uint4 vA = *(const uint4*)(base + (size_t)sA * CC);
        uint4 vB = *(const uint4*)(base + (size_t)sB * CC);
        uint4 vC = *(const uint4*)(base + (size_t)sC * CC);
        uint4 vD = *(const uint4*)(base + (size_t)sD * CC);
        const __half2* hA = (const __half2*)&vA;
        const __half2* hB = (const __half2*)&vB;
        const __half2* hC = (const __half2*)&vC;
        const __half2* hD = (const __half2*)&vD;
#pragma unroll
        for (int j = 0; j < 4; j++) {
            acc0[j] = __hadd2(acc0[j], hA[j]);
            acc1[j] = __hadd2(acc1[j], hB[j]);
            acc0[j] = __hadd2(acc0[j], hC[j]);
            acc1[j] = __hadd2(acc1[j], hD[j]);
        }
    }
    if (e + 2 <= s1) {
        const int sA = g_esrc[e];
        const int sB = g_esrc[e + 1];
        uint4 vA = *(const uint4*)(base + (size_t)sA * CC);
        uint4 vB = *(const uint4*)(base + (size_t)sB * CC);
        const __half2* hA = (const __half2*)&vA;
        const __half2* hB = (const __half2*)&vB;
#pragma unroll
        for (int j = 0; j < 4; j++) {
            acc0[j] = __hadd2(acc0[j], hA[j]);
            acc1[j] = __hadd2(acc1[j], hB[j]);
        }
        e += 2;
    }
    if (e < s1) {
        uint4 v = *(const uint4*)(base + (size_t)g_esrc[e] * CC);
        const __half2* hp = (const __half2*)&v;
#pragma unroll
        for (int j = 0; j < 4; j++) acc0[j] = __hadd2(acc0[j], hp[j]);
    }

    const float nrm = g_norm[node];
    const float sc  = alpha * nrm;

    float r[8];
#pragma unroll
    for (int j = 0; j < 4; j++) {
        float2 f0 = __half22float2(acc0[j]);
        float2 f1 = __half22float2(acc1[j]);
        r[2 * j]     = sc * (f0.x + f1.x);
        r[2 * j + 1] = sc * (f0.y + f1.y);
    }

    const size_t o = ((size_t)b * NN + node) * CC + c8;
    __half2 h[4];
    h[0] = __floats2half2_rn(r[0], r[1]);
    h[1] = __floats2half2_rn(r[2], r[3]);
    h[2] = __floats2half2_rn(r[4], r[5]);
    h[3] = __floats2half2_rn(r[6], r[7]);
    *(uint4*)(out_h + o) = *(uint4*)h;

    if (out_t != nullptr) {
        __half2 ht[4];
        ht[0] = __floats2half2_rn(nrm * r[0], nrm * r[1]);
        ht[1] = __floats2half2_rn(nrm * r[2], nrm * r[3]);
        ht[2] = __floats2half2_rn(nrm * r[4], nrm * r[5]);
        ht[3] = __floats2half2_rn(nrm * r[6], nrm * r[7]);
        *(uint4*)(out_t + o) = *(uint4*)ht;
    }
}

// ---------------- launch 6: fused dense via fp16 mma m16n8k16 ----------------
// Folded form:  h = relu( x*(W0-W2) + y1*W1 + z*(-2*W2) + bc ),  out = h*Wl + bl
// CTA: 128 rows x 64 cols, 512 threads (16 warps), warp tile 16x32.
// Canonical (R14) fragment layout — bank-conflict-free. Weight fragments are
// prebuilt by k_wprep; staging is a straight uint4 copy.
__global__ void __launch_bounds__(512, 2)
k_fused(const float* __restrict__ bc, const float* __restrict__ bl,
        float* __restrict__ out) {
    extern __shared__ float sm[];
    float* Af  = sm;                         // 12*8*32*4 = 12288 f (A frags, f16x2)
    float* Bf  = sm + NKT1 * 8 * 32 * 4;     // 12*32*20  =  7680 f (Wc frags, folded)
    float* Bl2 = Bf + NKT1 * 32 * BSTRIDE;   //  4*32*20  =  2560 f (Wl frags)
    float* bcs = Bl2 + NKT2 * 32 * BSTRIDE;  // 64
    float* bls = bcs + 64;                   // 64
    float* Hs  = Af;                         // overlay: 4*8*32*4 f (phase2 A)

    const int t    = threadIdx.x;
    const int lane = t & 31;
    const int w    = t >> 5;
    const int rowbase = blockIdx.x * TR;
    const int nrows = min(TR, NROWS - rowbase);

    // ---- stage Bf / Bl2: straight wide copies of prebuilt fragments ----
    for (int i = t; i < (NKT1 * 32 * BSTRIDE) / 4; i += 512)
        ((uint4*)Bf)[i] = ((const uint4*)g_bf)[i];
    for (int i = t; i < (NKT2 * 32 * BSTRIDE) / 4; i += 512)
        ((uint4*)Bl2)[i] = ((const uint4*)g_bl2)[i];
    if (t < 64) { bcs[t] = bc[t]; bls[t] = bl[t]; }

    // ---- stage Af: U = [xh | y1h | zh] rows [rowbase, rowbase+128) ----
    // canonical slot order (lane = gg*4+tt) — known conflict-free (R14)
    for (int idx = t; idx < NKT1 * 8 * 32; idx += 512) {
        const int kt  = idx >> 8;
        const int rem = idx & 255;
        const int rt  = rem >> 5;
        const int ln  = rem & 31;
        const int gg = ln >> 2, tt = ln & 3;
        const int r0 = rt * 16 + gg;
        const __half* p = (kt < 4) ? g_xh : (kt < 8) ? g_y1h : g_zh;
        const int c0 = (kt & 3) * 16 + 2 * tt;
        unsigned a0 = 0, a1 = 0, a2 = 0, a3 = 0;
        const __half* pr = p + (size_t)rowbase * CC;
        if (r0 < nrows) {
            a0 = *(const unsigned*)(pr + (size_t)r0 * CC + c0);
            a2 = *(const unsigned*)(pr + (size_t)r0 * CC + c0 + 8);
        }
        if (r0 + 8 < nrows) {
            a1 = *(const unsigned*)(pr + (size_t)(r0 + 8) * CC + c0);
            a3 = *(const unsigned*)(pr + (size_t)(r0 + 8) * CC + c0 + 8);
        }
        *(uint4*)(Af + idx * 4) = make_uint4(a0, a1, a2, a3);
    }
    __syncthreads();

    const int mtile = w >> 1;     // 0..7 -> rows 16*mtile
    const int nt2   = w & 1;      // 0..1 -> cols 32*nt2
    const int g = lane >> 2, tid = lane & 3;

    // ---- phase 1: h = U @ Wc_folded ----
    float c1[4][4];
#pragma unroll
    for (int n = 0; n < 4; n++)
#pragma unroll
        for (int q = 0; q < 4; q++) c1[n][q] = 0.f;

#pragma unroll
    for (int kt = 0; kt < NKT1; kt++) {
        const uint4 A = *(const uint4*)(Af + ((kt * 8 + mtile) * 32 + lane) * 4);
        const float* bp = Bf + (kt * 32 + lane) * BSTRIDE + nt2 * 8;
        const uint4 B0 = *(const uint4*)(bp);
        const uint4 B1 = *(const uint4*)(bp + 4);
        mma16(c1[0], A.x, A.y, A.z, A.w, B0.x, B0.y);
        mma16(c1[1], A.x, A.y, A.z, A.w, B0.z, B0.w);
        mma16(c1[2], A.x, A.y, A.z, A.w, B1.x, B1.y);
        mma16(c1[3], A.x, A.y, A.z, A.w, B1.z, B1.w);
    }
    __syncthreads();   // all Af reads complete before Hs overlay

    // ---- epilogue 1: bias + relu -> fp16 A-fragments into Hs ----
#pragma unroll
    for (int j = 0; j < 2; j++) {
        const int kt2 = 2 * nt2 + j;
        float v[4][2];
#pragma unroll
        for (int h = 0; h < 2; h++) {
            const int n = 2 * j + h;
            const int Cl = nt2 * 32 + n * 8 + 2 * tid;
            const float b0 = bcs[Cl], b1 = bcs[Cl + 1];
            v[2 * h][0]     = fmaxf(c1[n][0] + b0, 0.f);
            v[2 * h][1]     = fmaxf(c1[n][1] + b1, 0.f);
            v[2 * h + 1][0] = fmaxf(c1[n][2] + b0, 0.f);
            v[2 * h + 1][1] = fmaxf(c1[n][3] + b1, 0.f);
        }
        *(uint4*)(Hs + ((kt2 * 8 + mtile) * 32 + lane) * 4) =
            make_uint4(pkh2(v[0][0], v[0][1]), pkh2(v[1][0], v[1][1]),
                       pkh2(v[2][0], v[2][1]), pkh2(v[3][0], v[3][1]));
    }
    __syncthreads();

    // ---- phase 2: out = h @ Wl ----
    float c2[4][4];
#pragma unroll
    for (int n = 0; n < 4; n++)
#pragma unroll
        for (int q = 0; q < 4; q++) c2[n][q] = 0.f;

#pragma unroll
    for (int kt = 0; kt < NKT2; kt++) {
        const uint4 A = *(const uint4*)(Hs + ((kt * 8 + mtile) * 32 + lane) * 4);
        const float* bp = Bl2 + (kt * 32 + lane) * BSTRIDE + nt2 * 8;
        const uint4 B0 = *(const uint4*)(bp);
        const uint4 B1 = *(const uint4*)(bp + 4);
        mma16(c2[0], A.x, A.y, A.z, A.w, B0.x, B0.y);
        mma16(c2[1], A.x, A.y, A.z, A.w, B0.z, B0.w);
        mma16(c2[2], A.x, A.y, A.z, A.w, B1.x, B1.y);
        mma16(c2[3], A.x, A.y, A.z, A.w, B1.z, B1.w);
    }

    // ---- epilogue 2: bias + store ----
#pragma unroll
    for (int n = 0; n < 4; n++) {
        const int Cl = nt2 * 32 + n * 8 + 2 * tid;
        const float b0 = bls[Cl], b1 = bls[Cl + 1];
        const int Rl = mtile * 16 + g;
        if (Rl < nrows)
            *(float2*)(out + (size_t)(rowbase + Rl) * CC + Cl) =
                make_float2(c2[n][0] + b0, c2[n][1] + b1);
        if (Rl + 8 < nrows)
            *(float2*)(out + (size_t)(rowbase + Rl + 8) * CC + Cl) =
                make_float2(c2[n][2] + b0, c2[n][3] + b1);
    }
}

// ---------------- launch ----------------
extern "C" void kernel_launch(void* const* d_in, const int* in_sizes, int n_in,
                              void* d_out, int out_size) {
    const float* x   = (const float*)d_in[0];
    const int*   src = (const int*)d_in[1];
    const int*   dst = (const int*)d_in[2];
    const float* Wc  = (const float*)d_in[3];
    const float* bc  = (const float*)d_in[4];
    const float* Wl  = (const float*)d_in[5];
    const float* bl  = (const float*)d_in[6];
    float* out = (float*)d_out;

    const int fused_smem = (NKT1 * 8 * 32 * 4 + NKT1 * 32 * BSTRIDE +
                            NKT2 * 32 * BSTRIDE + 128) * 4;   // 90624 B
    static bool attr_set = false;
    if (!attr_set) {
        cudaFuncSetAttribute(k_fused, cudaFuncAttributeMaxDynamicSharedMemorySize,
                             fused_smem);
        attr_set = true;
    }

    __half *xt, *y1h, *y1t, *zh;
    cudaGetSymbolAddress((void**)&xt,  g_xt);
    cudaGetSymbolAddress((void**)&y1h, g_y1h);
    cudaGetSymbolAddress((void**)&y1t, g_y1t);
    cudaGetSymbolAddress((void**)&zh,  g_zh);

    // 0: build weight fragments once (independent of graph prep)
    k_wprep<<<2, 256>>>(Wc, Wl);
    // 1: degrees + edge ranks (g_deg zeroed at load / re-zeroed by k_fill3)
    k_degree<<<(EE + 255) / 256, 256>>>(dst);
    // 2: rowptr + norm
    k_emit2<<<SNB, SBS>>>();
    // 3: atomic-free edge fill + x -> (xh, xt) + re-zero deg
    k_fill3<<<(NROWS * CC / 8 + 255) / 256, 256>>>(src, dst, x);
    // 4: y1 = -norm[d] * sum(x~[src]) ; also y1t = norm*y1 for the next gather
    k_spmm_h<<<(NN + 7) / 8, 256>>>(xt, y1h, y1t, -1.f);
    // 5: z = norm[d] * sum(y1t[src]) = A y1   (y2 folded into GEMM weights)
    k_spmm_h<<<(NN + 7) / 8, 256>>>(y1t, zh, nullptr, 1.f);
    // 6: fused dense (fp16 tensor cores, prebuilt weight fragments)
    const int nblk = (NROWS + TR - 1) / TR;
    k_fused<<<nblk, 512, fused_smem>>>(bc, bl, out);
}